// round 14
// baseline (speedup 1.0000x reference)
#include <cuda_runtime.h>
#include <cuda_bf16.h>
#include <math.h>
#include <stddef.h>
#include <stdint.h>

#define NPTS 2048
#define BATCH 4
#define KNN_K 20
typedef unsigned long long ull;

// ---------------- scratch ----------------
__device__ float g_d[(size_t)BATCH*NPTS*NPTS];
__device__ int   g_idx[BATCH*NPTS*KNN_K];
__device__ float g_xx[BATCH*NPTS];
__device__ float g_tuv[(size_t)BATCH*NPTS*512];
__device__ float g_ut[BATCH*NPTS*256];
__device__ float g_wt[BATCH*NPTS*256];
__device__ float g_hmax[BATCH*NPTS*256];
__device__ float g_hmin[BATCH*NPTS*256];
__device__ float g_cat[(size_t)BATCH*512*NPTS];
__device__ float g_pf[(size_t)BATCH*1024*NPTS];
__device__ double g_s1[1024], g_s2[1024];
__device__ float g_scale[1024], g_shift[1024];
__device__ __nv_bfloat16 g_w5h[1024*512], g_w5l[1024*512];
__device__ __nv_bfloat16 g_cth[(size_t)BATCH*NPTS*512], g_ctl[(size_t)BATCH*NPTS*512];

__device__ __forceinline__ unsigned ordf(float f) {
    unsigned u = __float_as_uint(f);
    return (u & 0x80000000u) ? ~u : (u | 0x80000000u);
}
__device__ __forceinline__ void fma2(ull& d, ull a, ull b) {
    asm("fma.rn.f32x2 %0, %1, %2, %0;" : "+l"(d) : "l"(a), "l"(b));
}
__device__ __forceinline__ float lo32(ull v) { return __uint_as_float((unsigned)v); }
__device__ __forceinline__ float hi32(ull v) { return __uint_as_float((unsigned)(v >> 32)); }
__device__ __forceinline__ uint32_t smem_u32(const void* p) {
    uint32_t a;
    asm("{ .reg .u64 t; cvta.to.shared.u64 t, %1; cvt.u32.u64 %0, t; }" : "=r"(a) : "l"(p));
    return a;
}
__device__ __forceinline__ void ldm_x4(uint32_t& r0, uint32_t& r1, uint32_t& r2, uint32_t& r3, uint32_t a) {
    asm volatile("ldmatrix.sync.aligned.m8n8.x4.shared.b16 {%0,%1,%2,%3}, [%4];"
        : "=r"(r0), "=r"(r1), "=r"(r2), "=r"(r3) : "r"(a));
}
__device__ __forceinline__ void mma16816(float* c, const uint32_t* a, const uint32_t* bf) {
    asm volatile(
        "mma.sync.aligned.m16n8k16.row.col.f32.bf16.bf16.f32 "
        "{%0,%1,%2,%3}, {%4,%5,%6,%7}, {%8,%9}, {%0,%1,%2,%3};"
        : "+f"(c[0]), "+f"(c[1]), "+f"(c[2]), "+f"(c[3])
        : "r"(a[0]), "r"(a[1]), "r"(a[2]), "r"(a[3]), "r"(bf[0]), "r"(bf[1]));
}

// ---------------- mma.sync bf16 final GEMM ----------------
#define STR 40
#define TBUF (128*STR)
__global__ void __launch_bounds__(256) k_mma_final(
    const __nv_bfloat16* __restrict__ Wh, const __nv_bfloat16* __restrict__ Wl,
    const __nv_bfloat16* __restrict__ Xh, const __nv_bfloat16* __restrict__ Xl,
    float* __restrict__ pf)
{
    __shared__ __align__(16) __nv_bfloat16 sA[2][TBUF];
    __shared__ __align__(16) __nv_bfloat16 sB[2][TBUF];
    int tid = threadIdx.x, warp = tid >> 5, lane = tid & 31;
    int wm = warp & 1, wn = warp >> 1;
    int n0 = blockIdx.x * 128, m0 = blockIdx.y * 128, b = blockIdx.z;

    const __nv_bfloat16* Wsrc[2] = { Wh + (size_t)m0 * 512, Wl + (size_t)m0 * 512 };
    const __nv_bfloat16* Xsrc[2] = { Xh + ((size_t)b * NPTS + n0) * 512,
                                     Xl + ((size_t)b * NPTS + n0) * 512 };

    float acc[4][4][4];
#pragma unroll
    for (int i = 0; i < 4; i++)
#pragma unroll
        for (int j = 0; j < 4; j++)
#pragma unroll
            for (int q = 0; q < 4; q++) acc[i][j][q] = 0.f;

    uint32_t sAu = smem_u32(sA), sBu = smem_u32(sB);
    int r_ld = tid >> 1, c_ld = (tid & 1) * 2;

    auto ldchunk = [&](int it, int bufi) {
        int seg = it >> 4, kc = it & 15;
        const __nv_bfloat16* A = Wsrc[seg & 1];
        const __nv_bfloat16* B = Xsrc[seg >> 1];
#pragma unroll
        for (int h = 0; h < 2; h++) {
            int c = c_ld + h;
            float4 va = *(const float4*)(A + (size_t)r_ld * 512 + kc * 32 + c * 8);
            *(float4*)&sA[bufi][r_ld * STR + c * 8] = va;
            float4 vb = *(const float4*)(B + (size_t)r_ld * 512 + kc * 32 + c * 8);
            *(float4*)&sB[bufi][r_ld * STR + c * 8] = vb;
        }
    };

    ldchunk(0, 0);
    __syncthreads();
    int buf = 0;
    for (int it = 0; it < 64; it++) {
        if (it + 1 < 64) ldchunk(it + 1, buf ^ 1);
        int arow = lane & 15, ahalf = lane >> 4;
        int g = lane >> 3;
        int brow = (lane & 7) + (g >> 1) * 8, bcol = (g & 1) * 8;
#pragma unroll
        for (int ks = 0; ks < 2; ks++) {
            uint32_t afr[4][4], bfr[4][2];
#pragma unroll
            for (int i = 0; i < 4; i++) {
                uint32_t addr = sAu + (buf * TBUF + (wm * 64 + i * 16 + arow) * STR + ks * 16 + ahalf * 8) * 2;
                ldm_x4(afr[i][0], afr[i][1], afr[i][2], afr[i][3], addr);
            }
#pragma unroll
            for (int j = 0; j < 2; j++) {
                uint32_t addr = sBu + (buf * TBUF + (wn * 32 + j * 16 + brow) * STR + ks * 16 + bcol) * 2;
                uint32_t r0, r1, r2, r3;
                ldm_x4(r0, r1, r2, r3, addr);
                bfr[2*j][0] = r0; bfr[2*j][1] = r1; bfr[2*j+1][0] = r2; bfr[2*j+1][1] = r3;
            }
#pragma unroll
            for (int i = 0; i < 4; i++)
#pragma unroll
                for (int j = 0; j < 4; j++) mma16816(acc[i][j], afr[i], bfr[j]);
        }
        __syncthreads();
        buf ^= 1;
    }

    int rr = lane >> 2, cp = (lane & 3) * 2;
#pragma unroll
    for (int i = 0; i < 4; i++)
#pragma unroll
        for (int j = 0; j < 4; j++) {
            int m = m0 + wm * 64 + i * 16 + rr;
            int n = n0 + wn * 32 + j * 8 + cp;
            float* dst = pf + ((size_t)b * 1024 + m) * NPTS + n;
            *(float2*)dst = make_float2(acc[i][j][0], acc[i][j][1]);
            *(float2*)(dst + (size_t)8 * NPTS) = make_float2(acc[i][j][2], acc[i][j][3]);
        }
}

__global__ void k_w5cvt(const float* __restrict__ W, __nv_bfloat16* __restrict__ h,
                        __nv_bfloat16* __restrict__ l, int n) {
    int i = blockIdx.x * 256 + threadIdx.x;
    if (i < n) {
        float v = W[i];
        __nv_bfloat16 hi = __float2bfloat16(v);
        h[i] = hi; l[i] = __float2bfloat16(v - __bfloat162float(hi));
    }
}

__global__ void k_xx(const float* __restrict__ X, size_t xbs, int C,
                     float* __restrict__ xx, double* __restrict__ s1, double* __restrict__ s2) {
    int gid = blockIdx.x * 256 + threadIdx.x;
    int b = gid >> 11, n = gid & 2047;
    const float* Xb = X + (size_t)b * xbs;
    float s = 0.f;
    for (int c = 0; c < C; c++) { float v = Xb[(size_t)c * NPTS + n]; s += v * v; }
    xx[gid] = s;
    if (gid < 1024) { s1[gid] = 0.0; s2[gid] = 0.0; }
}

// symmetric distance, ONE batch per launch (pointers pre-offset)
__global__ void __launch_bounds__(256) k_dist2(const float* __restrict__ Xb,
                        const float* __restrict__ xxb, float* __restrict__ D, int C) {
    __shared__ float2 sN2[16][128];
    __shared__ float  sM[16][128];
    int pid = blockIdx.x;
    int ti = 0, rem = pid;
    while (rem >= 16 - ti) { rem -= 16 - ti; ti++; }
    int tj = ti + rem;
    int n0 = ti * 128, m0 = tj * 128;
    int t = threadIdx.x, tx = t & 15, ty = t >> 4;
    ull acc[8][4];
#pragma unroll
    for (int r = 0; r < 8; r++)
#pragma unroll
        for (int j = 0; j < 4; j++) acc[r][j] = 0ull;

    for (int k0 = 0; k0 < C; k0 += 16) {
        int kk = t >> 4, nl = (t & 15) * 8;
        float4 m0v = {0,0,0,0}, m1v = {0,0,0,0}, u0v = {0,0,0,0}, u1v = {0,0,0,0};
        if (k0 + kk < C) {
            const float4* sm_ = (const float4*)(Xb + (size_t)(k0+kk)*NPTS + m0 + nl);
            m0v = sm_[0]; m1v = sm_[1];
            const float4* sn_ = (const float4*)(Xb + (size_t)(k0+kk)*NPTS + n0 + nl);
            u0v = sn_[0]; u1v = sn_[1];
        }
        *(float4*)&sM[kk][nl] = m0v; *(float4*)&sM[kk][nl+4] = m1v;
        sN2[kk][nl+0] = make_float2(u0v.x, u0v.x); sN2[kk][nl+1] = make_float2(u0v.y, u0v.y);
        sN2[kk][nl+2] = make_float2(u0v.z, u0v.z); sN2[kk][nl+3] = make_float2(u0v.w, u0v.w);
        sN2[kk][nl+4] = make_float2(u1v.x, u1v.x); sN2[kk][nl+5] = make_float2(u1v.y, u1v.y);
        sN2[kk][nl+6] = make_float2(u1v.z, u1v.z); sN2[kk][nl+7] = make_float2(u1v.w, u1v.w);
        __syncthreads();
#pragma unroll
        for (int k2 = 0; k2 < 16; k2++) {
            ull a2[8], x2[4];
#pragma unroll
            for (int r = 0; r < 8; r++) a2[r] = *(const ull*)&sN2[k2][ty*8+r];
#pragma unroll
            for (int j = 0; j < 4; j++) x2[j] = *(const ull*)&sM[k2][j*32 + tx*2];
#pragma unroll
            for (int r = 0; r < 8; r++)
#pragma unroll
                for (int j = 0; j < 4; j++) fma2(acc[r][j], a2[r], x2[j]);
        }
        __syncthreads();
    }
    float xn[8], xm[8], dv[8][8];
#pragma unroll
    for (int r = 0; r < 8; r++) xn[r] = xxb[n0 + ty*8 + r];
#pragma unroll
    for (int j = 0; j < 4; j++) { xm[j*2] = xxb[m0 + j*32 + tx*2]; xm[j*2+1] = xxb[m0 + j*32 + tx*2 + 1]; }
#pragma unroll
    for (int r = 0; r < 8; r++)
#pragma unroll
        for (int j = 0; j < 4; j++) {
            dv[r][j*2]   = 2.f*lo32(acc[r][j]) - xn[r] - xm[j*2];
            dv[r][j*2+1] = 2.f*hi32(acc[r][j]) - xn[r] - xm[j*2+1];
        }
#pragma unroll
    for (int r = 0; r < 8; r++) {
        int n = n0 + ty*8 + r;
        float* dst = D + (size_t)n*NPTS + m0;
#pragma unroll
        for (int j = 0; j < 4; j++)
            *(float2*)&dst[j*32 + tx*2] = make_float2(dv[r][j*2], dv[r][j*2+1]);
    }
    if (ti != tj) {
#pragma unroll
        for (int j = 0; j < 4; j++)
#pragma unroll
            for (int h = 0; h < 2; h++) {
                int m = m0 + j*32 + tx*2 + h;
                float* dst = D + (size_t)m*NPTS + n0 + ty*8;
                int c = j*2 + h;
                *(float4*)dst       = make_float4(dv[0][c], dv[1][c], dv[2][c], dv[3][c]);
                *(float4*)(dst + 4) = make_float4(dv[4][c], dv[5][c], dv[6][c], dv[7][c]);
            }
    }
}

// ---------------- top-20 (R9 version), ONE batch per launch ----------------
__global__ void __launch_bounds__(256) k_topk(const float* __restrict__ D, int* __restrict__ IDX) {
    __shared__ unsigned sord[NPTS];
    __shared__ unsigned hist2[2][256];
    __shared__ unsigned incl[257];
    __shared__ int sm_m[128]; __shared__ unsigned sm_o[128];
    __shared__ int sh_out, sh_srv, sh_bkt, sh_rem;
    int n = blockIdx.x, t = threadIdx.x;
    int warp = t >> 5, lane = t & 31, hp = warp & 1;
    const float* row = D + (size_t)n*NPTS;
    int* out = IDX + (size_t)n*KNN_K;
    if (t == 0) { sh_out = 0; sh_srv = 0; }
    hist2[0][t] = 0u; hist2[1][t] = 0u;
    __syncthreads();
    const float4* row4 = (const float4*)row;
#pragma unroll
    for (int i = 0; i < 2; i++) {
        float4 v = row4[t + 256*i];
        int m = (t + 256*i)*4;
        unsigned u0 = ordf(v.x), u1 = ordf(v.y), u2 = ordf(v.z), u3 = ordf(v.w);
        sord[m] = u0; sord[m+1] = u1; sord[m+2] = u2; sord[m+3] = u3;
        atomicAdd(&hist2[hp][u0 >> 24], 1u);
        atomicAdd(&hist2[hp][u1 >> 24], 1u);
        atomicAdd(&hist2[hp][u2 >> 24], 1u);
        atomicAdd(&hist2[hp][u3 >> 24], 1u);
    }
    __syncthreads();
    if (warp == 0) {
        unsigned v[8], s = 0;
#pragma unroll
        for (int i = 7; i >= 0; i--) { v[i] = hist2[0][lane*8+i] + hist2[1][lane*8+i]; s += v[i]; }
        unsigned suf = s;
#pragma unroll
        for (int off = 1; off < 32; off <<= 1) {
            unsigned o = __shfl_down_sync(0xffffffffu, suf, off);
            if (lane + off < 32) suf += o;
        }
        unsigned acc = suf - s;
#pragma unroll
        for (int i = 7; i >= 0; i--) { acc += v[i]; incl[lane*8 + i] = acc; }
        if (lane == 0) incl[256] = 0;
    }
    __syncthreads();
    { unsigned ic = incl[t], ex = incl[t+1];
      if (ex < KNN_K && ic >= KNN_K) { sh_bkt = t; sh_rem = KNN_K - (int)ex; } }
    __syncthreads();
    unsigned b1 = (unsigned)sh_bkt; int rem = sh_rem;
    for (int m = t; m < NPTS; m += 256) {
        unsigned u = sord[m], by = u >> 24;
        if (by > b1) { int p = atomicAdd(&sh_out, 1); out[p] = m; }
        else if (by == b1) { int p = atomicAdd(&sh_srv, 1); if (p < 128) { sm_m[p] = m; sm_o[p] = u; } }
    }
    __syncthreads();
    int sc = sh_srv;
    if (sc <= 128) {
        for (int i = t; i < sc; i += 256) {
            unsigned myo = sm_o[i]; int mym = sm_m[i], r = 0;
            for (int j = 0; j < sc; j++) { unsigned oj = sm_o[j]; r += (oj > myo) || (oj == myo && sm_m[j] < mym); }
            if (r < rem) { int p = atomicAdd(&sh_out, 1); out[p] = mym; }
        }
    } else {
        unsigned prefix = b1 << 24;
        for (int shift = 16; shift >= 0; shift -= 8) {
            hist2[0][t] = 0u; __syncthreads();
            for (int m = t; m < NPTS; m += 256) {
                unsigned u = sord[m];
                if ((u >> (shift + 8)) == (prefix >> (shift + 8))) atomicAdd(&hist2[0][(u>>shift)&255u], 1u);
            }
            __syncthreads();
            if (warp == 0) {
                unsigned v[8], s = 0;
#pragma unroll
                for (int i = 7; i >= 0; i--) { v[i] = hist2[0][lane*8+i]; s += v[i]; }
                unsigned suf = s;
#pragma unroll
                for (int off = 1; off < 32; off <<= 1) {
                    unsigned o = __shfl_down_sync(0xffffffffu, suf, off);
                    if (lane + off < 32) suf += o;
                }
                unsigned acc = suf - s;
#pragma unroll
                for (int i = 7; i >= 0; i--) { acc += v[i]; incl[lane*8 + i] = acc; }
                if (lane == 0) incl[256] = 0;
            }
            __syncthreads();
            { unsigned ic = incl[t], ex = incl[t+1];
              if ((int)ex < rem && (int)ic >= rem) { sh_bkt = t; sh_rem = rem - (int)ex; } }
            __syncthreads();
            prefix |= ((unsigned)sh_bkt) << shift; rem = sh_rem; __syncthreads();
        }
        unsigned T = prefix;
        if (t == 0) sh_srv = 0; __syncthreads();
        for (int m = t; m < NPTS; m += 256) {
            unsigned u = sord[m];
            if ((u >> 24) == b1) {
                if (u > T) { int p = atomicAdd(&sh_out, 1); out[p] = m; }
                else if (u == T) { int p = atomicAdd(&sh_srv, 1); if (p < 128) sm_m[p] = m; }
            }
        }
        __syncthreads();
        int tc = min(sh_srv, 128);
        for (int i = t; i < tc; i += 256) {
            int mym = sm_m[i], r = 0;
            for (int j = 0; j < tc; j++) r += (sm_m[j] < mym);
            if (r < rem) { int p = atomicAdd(&sh_out, 1); out[p] = mym; }
        }
    }
}

// packed GEMM (pre-duplicated A in smem)
__global__ void __launch_bounds__(256) k_gemmp(const float* __restrict__ A, int lda, int osplit, int csplit,
                        const float* __restrict__ X, size_t xbs,
                        float* __restrict__ Out, size_t obs, int C) {
    __shared__ float2 sA2[16][128];
    __shared__ float  sX[16][128];
    int b = blockIdx.z, n0 = blockIdx.x * 128, r0 = blockIdx.y * 128;
    const float* Xb = X + (size_t)b * xbs;
    int t = threadIdx.x, tx = t & 15, ty = t >> 4;
    ull acc[8][4];
#pragma unroll
    for (int r = 0; r < 8; r++)
#pragma unroll
        for (int j = 0; j < 4; j++) acc[r][j] = 0ull;

    int ar = t >> 1, kb = (t & 1) * 8;
    int rr = r0 + ar;
    const float* Arow = (rr < osplit) ? (A + (size_t)rr * lda) : (A + (size_t)(rr - osplit) * lda + csplit);

    for (int k0 = 0; k0 < C; k0 += 16) {
        {
            int kk = t >> 4, nl = (t & 15) * 8;
            float4 x0 = {0,0,0,0}, x1 = {0,0,0,0};
            if (k0 + kk < C) {
                const float4* s = (const float4*)(Xb + (size_t)(k0+kk)*NPTS + n0 + nl);
                x0 = s[0]; x1 = s[1];
            }
            *(float4*)&sX[kk][nl] = x0; *(float4*)&sX[kk][nl+4] = x1;
        }
#pragma unroll
        for (int i = 0; i < 8; i++) {
            int k = k0 + kb + i;
            float a = (k < C) ? Arow[k] : 0.f;
            sA2[kb + i][ar] = make_float2(a, a);
        }
        __syncthreads();
#pragma unroll
        for (int k2 = 0; k2 < 16; k2++) {
            ull a2[8], x2[4];
#pragma unroll
            for (int r = 0; r < 8; r++) a2[r] = *(const ull*)&sA2[k2][ty*8+r];
#pragma unroll
            for (int j = 0; j < 4; j++) x2[j] = *(const ull*)&sX[k2][j*32 + tx*2];
#pragma unroll
            for (int r = 0; r < 8; r++)
#pragma unroll
                for (int j = 0; j < 4; j++) fma2(acc[r][j], a2[r], x2[j]);
        }
        __syncthreads();
    }
#pragma unroll
    for (int r = 0; r < 8; r++) {
        float* dst = Out + (size_t)b*obs + (size_t)(r0 + ty*8 + r)*NPTS + n0;
#pragma unroll
        for (int j = 0; j < 4; j++)
            *(float2*)&dst[j*32 + tx*2] = make_float2(lo32(acc[r][j]), hi32(acc[r][j]));
    }
}

__global__ void k_uvt(const float* __restrict__ TUV, float* __restrict__ ut, float* __restrict__ wt, int O) {
    __shared__ float tU[32][33], tV[32][33];
    int b = blockIdx.z, n0 = blockIdx.x * 32, o0 = blockIdx.y * 32;
    int tx = threadIdx.x, ty = threadIdx.y;
#pragma unroll
    for (int r = 0; r < 4; r++) {
        int ol = ty + r*8;
        size_t iu = ((size_t)(b*2*O) + o0 + ol)*NPTS + n0 + tx;
        tU[ol][tx] = TUV[iu]; tV[ol][tx] = TUV[iu + (size_t)O*NPTS];
    }
    __syncthreads();
#pragma unroll
    for (int r = 0; r < 4; r++) {
        int nl = ty + r*8;
        size_t i = ((size_t)b*NPTS + n0 + nl)*O + o0 + tx;
        float u = tU[tx][nl]; ut[i] = u; wt[i] = tV[tx][nl] - u;
    }
}

__global__ void k_gather(const float* __restrict__ ut, const float* __restrict__ wt,
                         const int* __restrict__ IDX,
                         float* __restrict__ hmax, float* __restrict__ hmin,
                         double* __restrict__ s1g, double* __restrict__ s2g, int O) {
    int b = blockIdx.y, n0 = blockIdx.x * 8, o = threadIdx.x;
    __shared__ int sI[8*KNN_K];
    for (int l = o; l < 8*KNN_K; l += blockDim.x)
        sI[l] = IDX[((size_t)b*NPTS + n0 + l/KNN_K)*KNN_K + (l%KNN_K)];
    __syncthreads();
    const float* utb = ut + (size_t)b*NPTS*O;
    double s1a = 0.0, s2a = 0.0;
    for (int nn = 0; nn < 8; nn++) {
        float mx = -INFINITY, mn = INFINITY; float s1 = 0.f, s2 = 0.f;
#pragma unroll
        for (int k = 0; k < KNN_K; k++) {
            float v = utb[(size_t)sI[nn*KNN_K+k]*O + o];
            mx = fmaxf(mx, v); mn = fminf(mn, v); s1 += v; s2 += v*v;
        }
        size_t i = ((size_t)b*NPTS + n0 + nn)*O + o;
        float w = wt[i];
        hmax[i] = mx + w; hmin[i] = mn + w;
        s1a += (double)s1 + 20.0*(double)w;
        s2a += (double)s2 + 2.0*(double)w*(double)s1 + 20.0*(double)w*(double)w;
    }
    atomicAdd(&s1g[o], s1a); atomicAdd(&s2g[o], s2a);
}

__global__ void k_statsfin(const double* __restrict__ s1, const double* __restrict__ s2,
                           const float* __restrict__ g, const float* __restrict__ bb,
                           float* __restrict__ scale, float* __restrict__ shift, double cnt, int O) {
    int o = blockIdx.x * 256 + threadIdx.x;
    if (o >= O) return;
    double mean = s1[o] / cnt;
    double var = s2[o] / cnt - mean * mean;
    float s = g[o] * (float)(1.0 / sqrt(var + 1e-5));
    scale[o] = s; shift[o] = bb[o] - (float)mean * s;
}

__global__ void k_apply(const float* __restrict__ hmax, const float* __restrict__ hmin,
                        const float* __restrict__ scale, const float* __restrict__ shift,
                        float* __restrict__ xcat,
                        __nv_bfloat16* __restrict__ cth, __nv_bfloat16* __restrict__ ctl,
                        int O, int rowOff) {
    __shared__ float tile[32][33];
    int b = blockIdx.z, n0 = blockIdx.x * 32, o0 = blockIdx.y * 32;
    int tx = threadIdx.x, ty = threadIdx.y;
#pragma unroll
    for (int r = 0; r < 4; r++) {
        int nl = ty + r*8; int o = o0 + tx;
        float s = scale[o], t0 = shift[o];
        size_t i = ((size_t)b*NPTS + n0 + nl)*O + o;
        float hv = (s >= 0.f) ? hmax[i] : hmin[i];
        float y = s*hv + t0; y = (y >= 0.f) ? y : 0.2f*y;
        tile[nl][tx] = y;
        size_t ct = ((size_t)b*NPTS + n0 + nl)*512 + rowOff + o;
        __nv_bfloat16 hi = __float2bfloat16(y);
        cth[ct] = hi; ctl[ct] = __float2bfloat16(y - __bfloat162float(hi));
    }
    __syncthreads();
#pragma unroll
    for (int r = 0; r < 4; r++) {
        int ol = ty + r*8;
        xcat[(size_t)b*512*NPTS + (size_t)(rowOff + o0 + ol)*NPTS + n0 + tx] = tile[tx][ol];
    }
}

__global__ void k_fstats(const float* __restrict__ pf, double* __restrict__ s1o, double* __restrict__ s2o) {
    int o = blockIdx.x, t = threadIdx.x;
    double s1 = 0.0, s2 = 0.0;
    for (int l = t; l < BATCH*NPTS; l += 256) {
        int b = l >> 11, n = l & 2047;
        float v = pf[((size_t)b*1024 + o)*NPTS + n];
        s1 += (double)v; s2 += (double)v*(double)v;
    }
    __shared__ double r1[256], r2[256];
    r1[t] = s1; r2[t] = s2; __syncthreads();
    for (int off = 128; off; off >>= 1) {
        if (t < off) { r1[t] += r1[t+off]; r2[t] += r2[t+off]; }
        __syncthreads();
    }
    if (t == 0) { s1o[o] = r1[0]; s2o[o] = r2[0]; }
}

__global__ void k_out(const float* __restrict__ pf, const float* __restrict__ scale,
                      const float* __restrict__ shift, float* __restrict__ out) {
    int o = blockIdx.x, b = blockIdx.y, t = threadIdx.x;
    float s = scale[o], t0 = shift[o];
    const float* base = pf + ((size_t)b*1024 + o)*NPTS;
    { float v = base[t]; float y = s*v + t0; y = (y >= 0.f) ? y : 0.2f*y;
      out[(size_t)b*131072 + o*128 + t] = y; }
    int w = t >> 5, lane = t & 31;
#pragma unroll
    for (int i = 0; i < 4; i++) {
        int nb = w*4 + i;
        float mx = -INFINITY;
#pragma unroll
        for (int j = 0; j < 4; j++) {
            float v = base[nb*128 + lane + 32*j];
            float y = s*v + t0; y = (y >= 0.f) ? y : 0.2f*y;
            mx = fmaxf(mx, y);
        }
#pragma unroll
        for (int off = 16; off; off >>= 1) mx = fmaxf(mx, __shfl_xor_sync(0xffffffffu, mx, off));
        if (lane == 0) {
            size_t gb = 524288 + (size_t)b*32768;
            out[gb + (size_t)o*16 + nb] = mx;
            out[gb + (size_t)(o+1024)*16 + nb] = mx;
        }
    }
}

extern "C" void kernel_launch(void* const* d_in, const int* in_sizes, int n_in,
                              void* d_out, int out_size) {
    const float* x  = (const float*)d_in[0];
    const float* W[5]; for (int i = 0; i < 5; i++) W[i] = (const float*)d_in[1+i];
    const float* G[5]; const float* Bs[5];
    for (int i = 0; i < 5; i++) { G[i] = (const float*)d_in[6+2*i]; Bs[i] = (const float*)d_in[7+2*i]; }
    float* out = (float*)d_out;

    float *pD, *pXX, *pTUV, *pUT, *pWT, *pHX, *pHN, *pCAT, *pPF, *pSC, *pSH;
    double *pS1, *pS2;
    int* pIDX;
    __nv_bfloat16 *pW5h, *pW5l, *pCth, *pCtl;
    cudaGetSymbolAddress((void**)&pD, g_d);     cudaGetSymbolAddress((void**)&pXX, g_xx);
    cudaGetSymbolAddress((void**)&pTUV, g_tuv);
    cudaGetSymbolAddress((void**)&pUT, g_ut);   cudaGetSymbolAddress((void**)&pWT, g_wt);
    cudaGetSymbolAddress((void**)&pHX, g_hmax); cudaGetSymbolAddress((void**)&pHN, g_hmin);
    cudaGetSymbolAddress((void**)&pCAT, g_cat); cudaGetSymbolAddress((void**)&pPF, g_pf);
    cudaGetSymbolAddress((void**)&pS1, g_s1);   cudaGetSymbolAddress((void**)&pS2, g_s2);
    cudaGetSymbolAddress((void**)&pSC, g_scale); cudaGetSymbolAddress((void**)&pSH, g_shift);
    cudaGetSymbolAddress((void**)&pIDX, g_idx);
    cudaGetSymbolAddress((void**)&pW5h, g_w5h); cudaGetSymbolAddress((void**)&pW5l, g_w5l);
    cudaGetSymbolAddress((void**)&pCth, g_cth); cudaGetSymbolAddress((void**)&pCtl, g_ctl);

    k_w5cvt<<<2048, 256>>>(W[4], pW5h, pW5l, 1024*512);

    struct Layer { const float* X; size_t xbs; int C; int O; const float* Wm; int rowOff; };
    Layer L[4] = {
        { x,                        (size_t)3*NPTS,   3,   64,  W[0], 0   },
        { pCAT,                     (size_t)512*NPTS, 64,  64,  W[1], 64  },
        { pCAT + (size_t)64*NPTS,   (size_t)512*NPTS, 64,  128, W[2], 128 },
        { pCAT + (size_t)128*NPTS,  (size_t)512*NPTS, 128, 256, W[3], 256 },
    };

    for (int li = 0; li < 4; li++) {
        const Layer& l = L[li];
        k_xx<<<32, 256>>>(l.X, l.xbs, l.C, pXX, pS1, pS2);
        // per-batch dist -> topk interleave: one batch's D (64MB) stays L2-resident
        for (int b = 0; b < BATCH; b++) {
            float* Db = pD + (size_t)b * NPTS * NPTS;
            k_dist2<<<136, 256>>>(l.X + (size_t)b * l.xbs, pXX + (size_t)b * NPTS, Db, l.C);
            k_topk<<<NPTS, 256>>>(Db, pIDX + (size_t)b * NPTS * KNN_K);
        }
        size_t obs = (size_t)(2*l.O) * NPTS;
        k_gemmp<<<dim3(16, (2*l.O)/128, BATCH), 256>>>(l.Wm, 2*l.C, l.O, l.C,
                                                       l.X, l.xbs, pTUV, obs, l.C);
        k_uvt<<<dim3(64, l.O/32, BATCH), dim3(32, 8)>>>(pTUV, pUT, pWT, l.O);
        k_gather<<<dim3(256, BATCH), l.O>>>(pUT, pWT, pIDX, pHX, pHN, pS1, pS2, l.O);
        k_statsfin<<<(l.O + 255)/256, 256>>>(pS1, pS2, G[li], Bs[li], pSC, pSH,
                                             (double)BATCH*NPTS*KNN_K, l.O);
        k_apply<<<dim3(64, l.O/32, BATCH), dim3(32, 8)>>>(pHX, pHN, pSC, pSH, pCAT,
                                                          pCth, pCtl, l.O, l.rowOff);
    }

    k_mma_final<<<dim3(16, 8, BATCH), 256>>>(pW5h, pW5l, pCth, pCtl, pPF);
    k_fstats<<<1024, 256>>>(pPF, pS1, pS2);
    k_statsfin<<<4, 256>>>(pS1, pS2, G[4], Bs[4], pSC, pSH, (double)BATCH*NPTS, 1024);
    k_out<<<dim3(1024, BATCH), 128>>>(pPF, pSC, pSH, out);
}

// round 15
// speedup vs baseline: 1.2137x; 1.2137x over previous
#include <cuda_runtime.h>
#include <cuda_bf16.h>
#include <math.h>
#include <stddef.h>
#include <stdint.h>

#define NPTS 2048
#define BATCH 4
#define KNN_K 20
typedef unsigned long long ull;

// ---------------- scratch ----------------
__device__ float g_d[(size_t)BATCH*NPTS*NPTS];
__device__ int   g_idx[BATCH*NPTS*KNN_K];
__device__ float g_xx[BATCH*NPTS];
__device__ float g_tuv[(size_t)BATCH*NPTS*512];
__device__ float g_ut[BATCH*NPTS*256];
__device__ float g_wt[BATCH*NPTS*256];
__device__ float g_hmax[BATCH*NPTS*256];
__device__ float g_hmin[BATCH*NPTS*256];
__device__ float g_cat[(size_t)BATCH*512*NPTS];
__device__ float g_pf[(size_t)BATCH*1024*NPTS];
__device__ double g_s1[1024], g_s2[1024];
__device__ float g_scale[1024], g_shift[1024];
__device__ __nv_bfloat16 g_w5h[1024*512], g_w5l[1024*512];
__device__ __nv_bfloat16 g_cth[(size_t)BATCH*NPTS*512], g_ctl[(size_t)BATCH*NPTS*512];

__device__ __forceinline__ unsigned ordf(float f) {
    unsigned u = __float_as_uint(f);
    return (u & 0x80000000u) ? ~u : (u | 0x80000000u);
}
__device__ __forceinline__ void fma2(ull& d, ull a, ull b) {
    asm("fma.rn.f32x2 %0, %1, %2, %0;" : "+l"(d) : "l"(a), "l"(b));
}
__device__ __forceinline__ float lo32(ull v) { return __uint_as_float((unsigned)v); }
__device__ __forceinline__ float hi32(ull v) { return __uint_as_float((unsigned)(v >> 32)); }
__device__ __forceinline__ uint32_t smem_u32(const void* p) {
    uint32_t a;
    asm("{ .reg .u64 t; cvta.to.shared.u64 t, %1; cvt.u32.u64 %0, t; }" : "=r"(a) : "l"(p));
    return a;
}
__device__ __forceinline__ void ldm_x4(uint32_t& r0, uint32_t& r1, uint32_t& r2, uint32_t& r3, uint32_t a) {
    asm volatile("ldmatrix.sync.aligned.m8n8.x4.shared.b16 {%0,%1,%2,%3}, [%4];"
        : "=r"(r0), "=r"(r1), "=r"(r2), "=r"(r3) : "r"(a));
}
__device__ __forceinline__ void mma16816(float* c, const uint32_t* a, const uint32_t* bf) {
    asm volatile(
        "mma.sync.aligned.m16n8k16.row.col.f32.bf16.bf16.f32 "
        "{%0,%1,%2,%3}, {%4,%5,%6,%7}, {%8,%9}, {%0,%1,%2,%3};"
        : "+f"(c[0]), "+f"(c[1]), "+f"(c[2]), "+f"(c[3])
        : "r"(a[0]), "r"(a[1]), "r"(a[2]), "r"(a[3]), "r"(bf[0]), "r"(bf[1]));
}

// ---------------- mma.sync bf16 final GEMM (3-term split: Wh*Xh + Wl*Xh + Wh*Xl) ----------------
#define STR 40
#define TBUF (128*STR)
__global__ void __launch_bounds__(256) k_mma_final(
    const __nv_bfloat16* __restrict__ Wh, const __nv_bfloat16* __restrict__ Wl,
    const __nv_bfloat16* __restrict__ Xh, const __nv_bfloat16* __restrict__ Xl,
    float* __restrict__ pf)
{
    __shared__ __align__(16) __nv_bfloat16 sA[2][TBUF];
    __shared__ __align__(16) __nv_bfloat16 sB[2][TBUF];
    int tid = threadIdx.x, warp = tid >> 5, lane = tid & 31;
    int wm = warp & 1, wn = warp >> 1;
    int n0 = blockIdx.x * 128, m0 = blockIdx.y * 128, b = blockIdx.z;

    // segment s: A from Wa[s], B from Xb[s];  s=0: Wh,Xh  s=1: Wl,Xh  s=2: Wh,Xl
    const __nv_bfloat16* Wa[3] = { Wh + (size_t)m0 * 512, Wl + (size_t)m0 * 512, Wh + (size_t)m0 * 512 };
    const __nv_bfloat16* Xb3[3] = { Xh + ((size_t)b * NPTS + n0) * 512,
                                    Xh + ((size_t)b * NPTS + n0) * 512,
                                    Xl + ((size_t)b * NPTS + n0) * 512 };

    float acc[4][4][4];
#pragma unroll
    for (int i = 0; i < 4; i++)
#pragma unroll
        for (int j = 0; j < 4; j++)
#pragma unroll
            for (int q = 0; q < 4; q++) acc[i][j][q] = 0.f;

    uint32_t sAu = smem_u32(sA), sBu = smem_u32(sB);
    int r_ld = tid >> 1, c_ld = (tid & 1) * 2;

    auto ldchunk = [&](int it, int bufi) {
        int seg = it >> 4, kc = it & 15;
        const __nv_bfloat16* A = Wa[seg];
        const __nv_bfloat16* B = Xb3[seg];
#pragma unroll
        for (int h = 0; h < 2; h++) {
            int c = c_ld + h;
            float4 va = *(const float4*)(A + (size_t)r_ld * 512 + kc * 32 + c * 8);
            *(float4*)&sA[bufi][r_ld * STR + c * 8] = va;
            float4 vb = *(const float4*)(B + (size_t)r_ld * 512 + kc * 32 + c * 8);
            *(float4*)&sB[bufi][r_ld * STR + c * 8] = vb;
        }
    };

    ldchunk(0, 0);
    __syncthreads();
    int buf = 0;
    for (int it = 0; it < 48; it++) {
        if (it + 1 < 48) ldchunk(it + 1, buf ^ 1);
        int arow = lane & 15, ahalf = lane >> 4;
        int g = lane >> 3;
        int brow = (lane & 7) + (g >> 1) * 8, bcol = (g & 1) * 8;
#pragma unroll
        for (int ks = 0; ks < 2; ks++) {
            uint32_t afr[4][4], bfr[4][2];
#pragma unroll
            for (int i = 0; i < 4; i++) {
                uint32_t addr = sAu + (buf * TBUF + (wm * 64 + i * 16 + arow) * STR + ks * 16 + ahalf * 8) * 2;
                ldm_x4(afr[i][0], afr[i][1], afr[i][2], afr[i][3], addr);
            }
#pragma unroll
            for (int j = 0; j < 2; j++) {
                uint32_t addr = sBu + (buf * TBUF + (wn * 32 + j * 16 + brow) * STR + ks * 16 + bcol) * 2;
                uint32_t r0, r1, r2, r3;
                ldm_x4(r0, r1, r2, r3, addr);
                bfr[2*j][0] = r0; bfr[2*j][1] = r1; bfr[2*j+1][0] = r2; bfr[2*j+1][1] = r3;
            }
#pragma unroll
            for (int i = 0; i < 4; i++)
#pragma unroll
                for (int j = 0; j < 4; j++) mma16816(acc[i][j], afr[i], bfr[j]);
        }
        __syncthreads();
        buf ^= 1;
    }

    int rr = lane >> 2, cp = (lane & 3) * 2;
#pragma unroll
    for (int i = 0; i < 4; i++)
#pragma unroll
        for (int j = 0; j < 4; j++) {
            int m = m0 + wm * 64 + i * 16 + rr;
            int n = n0 + wn * 32 + j * 8 + cp;
            float* dst = pf + ((size_t)b * 1024 + m) * NPTS + n;
            *(float2*)dst = make_float2(acc[i][j][0], acc[i][j][1]);
            *(float2*)(dst + (size_t)8 * NPTS) = make_float2(acc[i][j][2], acc[i][j][3]);
        }
}

__global__ void k_w5cvt(const float* __restrict__ W, __nv_bfloat16* __restrict__ h,
                        __nv_bfloat16* __restrict__ l, int n) {
    int i = blockIdx.x * 256 + threadIdx.x;
    if (i < n) {
        float v = W[i];
        __nv_bfloat16 hi = __float2bfloat16(v);
        h[i] = hi; l[i] = __float2bfloat16(v - __bfloat162float(hi));
    }
}

__global__ void k_xx(const float* __restrict__ X, size_t xbs, int C,
                     float* __restrict__ xx, double* __restrict__ s1, double* __restrict__ s2) {
    int gid = blockIdx.x * 256 + threadIdx.x;
    int b = gid >> 11, n = gid & 2047;
    const float* Xb = X + (size_t)b * xbs;
    float s = 0.f;
    for (int c = 0; c < C; c++) { float v = Xb[(size_t)c * NPTS + n]; s += v * v; }
    xx[gid] = s;
    if (gid < 1024) { s1[gid] = 0.0; s2[gid] = 0.0; }
}

// symmetric distance (exact fp32, pre-duplicated A in smem)
__global__ void __launch_bounds__(256) k_dist2(const float* __restrict__ X, size_t xbs,
                        const float* __restrict__ xx, float* __restrict__ D, int C) {
    __shared__ float2 sN2[16][128];
    __shared__ float  sM[16][128];
    int b = blockIdx.y;
    int pid = blockIdx.x;
    int ti = 0, rem = pid;
    while (rem >= 16 - ti) { rem -= 16 - ti; ti++; }
    int tj = ti + rem;
    int n0 = ti * 128, m0 = tj * 128;
    const float* Xb = X + (size_t)b * xbs;
    int t = threadIdx.x, tx = t & 15, ty = t >> 4;
    ull acc[8][4];
#pragma unroll
    for (int r = 0; r < 8; r++)
#pragma unroll
        for (int j = 0; j < 4; j++) acc[r][j] = 0ull;

    for (int k0 = 0; k0 < C; k0 += 16) {
        int kk = t >> 4, nl = (t & 15) * 8;
        float4 m0v = {0,0,0,0}, m1v = {0,0,0,0}, u0v = {0,0,0,0}, u1v = {0,0,0,0};
        if (k0 + kk < C) {
            const float4* sm_ = (const float4*)(Xb + (size_t)(k0+kk)*NPTS + m0 + nl);
            m0v = sm_[0]; m1v = sm_[1];
            const float4* sn_ = (const float4*)(Xb + (size_t)(k0+kk)*NPTS + n0 + nl);
            u0v = sn_[0]; u1v = sn_[1];
        }
        *(float4*)&sM[kk][nl] = m0v; *(float4*)&sM[kk][nl+4] = m1v;
        sN2[kk][nl+0] = make_float2(u0v.x, u0v.x); sN2[kk][nl+1] = make_float2(u0v.y, u0v.y);
        sN2[kk][nl+2] = make_float2(u0v.z, u0v.z); sN2[kk][nl+3] = make_float2(u0v.w, u0v.w);
        sN2[kk][nl+4] = make_float2(u1v.x, u1v.x); sN2[kk][nl+5] = make_float2(u1v.y, u1v.y);
        sN2[kk][nl+6] = make_float2(u1v.z, u1v.z); sN2[kk][nl+7] = make_float2(u1v.w, u1v.w);
        __syncthreads();
#pragma unroll
        for (int k2 = 0; k2 < 16; k2++) {
            ull a2[8], x2[4];
#pragma unroll
            for (int r = 0; r < 8; r++) a2[r] = *(const ull*)&sN2[k2][ty*8+r];
#pragma unroll
            for (int j = 0; j < 4; j++) x2[j] = *(const ull*)&sM[k2][j*32 + tx*2];
#pragma unroll
            for (int r = 0; r < 8; r++)
#pragma unroll
                for (int j = 0; j < 4; j++) fma2(acc[r][j], a2[r], x2[j]);
        }
        __syncthreads();
    }
    const float* xxb = xx + b * NPTS;
    float xn[8], xm[8], dv[8][8];
#pragma unroll
    for (int r = 0; r < 8; r++) xn[r] = xxb[n0 + ty*8 + r];
#pragma unroll
    for (int j = 0; j < 4; j++) { xm[j*2] = xxb[m0 + j*32 + tx*2]; xm[j*2+1] = xxb[m0 + j*32 + tx*2 + 1]; }
#pragma unroll
    for (int r = 0; r < 8; r++)
#pragma unroll
        for (int j = 0; j < 4; j++) {
            dv[r][j*2]   = 2.f*lo32(acc[r][j]) - xn[r] - xm[j*2];
            dv[r][j*2+1] = 2.f*hi32(acc[r][j]) - xn[r] - xm[j*2+1];
        }
#pragma unroll
    for (int r = 0; r < 8; r++) {
        int n = n0 + ty*8 + r;
        float* dst = D + ((size_t)b*NPTS + n)*NPTS + m0;
#pragma unroll
        for (int j = 0; j < 4; j++)
            *(float2*)&dst[j*32 + tx*2] = make_float2(dv[r][j*2], dv[r][j*2+1]);
    }
    if (ti != tj) {
#pragma unroll
        for (int j = 0; j < 4; j++)
#pragma unroll
            for (int h = 0; h < 2; h++) {
                int m = m0 + j*32 + tx*2 + h;
                float* dst = D + ((size_t)b*NPTS + m)*NPTS + n0 + ty*8;
                int c = j*2 + h;
                *(float4*)dst       = make_float4(dv[0][c], dv[1][c], dv[2][c], dv[3][c]);
                *(float4*)(dst + 4) = make_float4(dv[4][c], dv[5][c], dv[6][c], dv[7][c]);
            }
    }
}

// ---------------- top-20 (R9 version: sord smem, dual hist, shuffle scan) ----------------
__global__ void __launch_bounds__(256) k_topk(const float* __restrict__ D, int* __restrict__ IDX) {
    __shared__ unsigned sord[NPTS];
    __shared__ unsigned hist2[2][256];
    __shared__ unsigned incl[257];
    __shared__ int sm_m[128]; __shared__ unsigned sm_o[128];
    __shared__ int sh_out, sh_srv, sh_bkt, sh_rem;
    int n = blockIdx.x, b = blockIdx.y, t = threadIdx.x;
    int warp = t >> 5, lane = t & 31, hp = warp & 1;
    const float* row = D + ((size_t)b*NPTS + n)*NPTS;
    int* out = IDX + ((size_t)b*NPTS + n)*KNN_K;
    if (t == 0) { sh_out = 0; sh_srv = 0; }
    hist2[0][t] = 0u; hist2[1][t] = 0u;
    __syncthreads();
    const float4* row4 = (const float4*)row;
#pragma unroll
    for (int i = 0; i < 2; i++) {
        float4 v = row4[t + 256*i];
        int m = (t + 256*i)*4;
        unsigned u0 = ordf(v.x), u1 = ordf(v.y), u2 = ordf(v.z), u3 = ordf(v.w);
        sord[m] = u0; sord[m+1] = u1; sord[m+2] = u2; sord[m+3] = u3;
        atomicAdd(&hist2[hp][u0 >> 24], 1u);
        atomicAdd(&hist2[hp][u1 >> 24], 1u);
        atomicAdd(&hist2[hp][u2 >> 24], 1u);
        atomicAdd(&hist2[hp][u3 >> 24], 1u);
    }
    __syncthreads();
    if (warp == 0) {
        unsigned v[8], s = 0;
#pragma unroll
        for (int i = 7; i >= 0; i--) { v[i] = hist2[0][lane*8+i] + hist2[1][lane*8+i]; s += v[i]; }
        unsigned suf = s;
#pragma unroll
        for (int off = 1; off < 32; off <<= 1) {
            unsigned o = __shfl_down_sync(0xffffffffu, suf, off);
            if (lane + off < 32) suf += o;
        }
        unsigned acc = suf - s;
#pragma unroll
        for (int i = 7; i >= 0; i--) { acc += v[i]; incl[lane*8 + i] = acc; }
        if (lane == 0) incl[256] = 0;
    }
    __syncthreads();
    { unsigned ic = incl[t], ex = incl[t+1];
      if (ex < KNN_K && ic >= KNN_K) { sh_bkt = t; sh_rem = KNN_K - (int)ex; } }
    __syncthreads();
    unsigned b1 = (unsigned)sh_bkt; int rem = sh_rem;
    for (int m = t; m < NPTS; m += 256) {
        unsigned u = sord[m], by = u >> 24;
        if (by > b1) { int p = atomicAdd(&sh_out, 1); out[p] = m; }
        else if (by == b1) { int p = atomicAdd(&sh_srv, 1); if (p < 128) { sm_m[p] = m; sm_o[p] = u; } }
    }
    __syncthreads();
    int sc = sh_srv;
    if (sc <= 128) {
        for (int i = t; i < sc; i += 256) {
            unsigned myo = sm_o[i]; int mym = sm_m[i], r = 0;
            for (int j = 0; j < sc; j++) { unsigned oj = sm_o[j]; r += (oj > myo) || (oj == myo && sm_m[j] < mym); }
            if (r < rem) { int p = atomicAdd(&sh_out, 1); out[p] = mym; }
        }
    } else {
        unsigned prefix = b1 << 24;
        for (int shift = 16; shift >= 0; shift -= 8) {
            hist2[0][t] = 0u; __syncthreads();
            for (int m = t; m < NPTS; m += 256) {
                unsigned u = sord[m];
                if ((u >> (shift + 8)) == (prefix >> (shift + 8))) atomicAdd(&hist2[0][(u>>shift)&255u], 1u);
            }
            __syncthreads();
            if (warp == 0) {
                unsigned v[8], s = 0;
#pragma unroll
                for (int i = 7; i >= 0; i--) { v[i] = hist2[0][lane*8+i]; s += v[i]; }
                unsigned suf = s;
#pragma unroll
                for (int off = 1; off < 32; off <<= 1) {
                    unsigned o = __shfl_down_sync(0xffffffffu, suf, off);
                    if (lane + off < 32) suf += o;
                }
                unsigned acc = suf - s;
#pragma unroll
                for (int i = 7; i >= 0; i--) { acc += v[i]; incl[lane*8 + i] = acc; }
                if (lane == 0) incl[256] = 0;
            }
            __syncthreads();
            { unsigned ic = incl[t], ex = incl[t+1];
              if ((int)ex < rem && (int)ic >= rem) { sh_bkt = t; sh_rem = rem - (int)ex; } }
            __syncthreads();
            prefix |= ((unsigned)sh_bkt) << shift; rem = sh_rem; __syncthreads();
        }
        unsigned T = prefix;
        if (t == 0) sh_srv = 0; __syncthreads();
        for (int m = t; m < NPTS; m += 256) {
            unsigned u = sord[m];
            if ((u >> 24) == b1) {
                if (u > T) { int p = atomicAdd(&sh_out, 1); out[p] = m; }
                else if (u == T) { int p = atomicAdd(&sh_srv, 1); if (p < 128) sm_m[p] = m; }
            }
        }
        __syncthreads();
        int tc = min(sh_srv, 128);
        for (int i = t; i < tc; i += 256) {
            int mym = sm_m[i], r = 0;
            for (int j = 0; j < tc; j++) r += (sm_m[j] < mym);
            if (r < rem) { int p = atomicAdd(&sh_out, 1); out[p] = mym; }
        }
    }
}

// packed GEMM (pre-duplicated A in smem)
__global__ void __launch_bounds__(256) k_gemmp(const float* __restrict__ A, int lda, int osplit, int csplit,
                        const float* __restrict__ X, size_t xbs,
                        float* __restrict__ Out, size_t obs, int C) {
    __shared__ float2 sA2[16][128];
    __shared__ float  sX[16][128];
    int b = blockIdx.z, n0 = blockIdx.x * 128, r0 = blockIdx.y * 128;
    const float* Xb = X + (size_t)b * xbs;
    int t = threadIdx.x, tx = t & 15, ty = t >> 4;
    ull acc[8][4];
#pragma unroll
    for (int r = 0; r < 8; r++)
#pragma unroll
        for (int j = 0; j < 4; j++) acc[r][j] = 0ull;

    int ar = t >> 1, kb = (t & 1) * 8;
    int rr = r0 + ar;
    const float* Arow = (rr < osplit) ? (A + (size_t)rr * lda) : (A + (size_t)(rr - osplit) * lda + csplit);

    for (int k0 = 0; k0 < C; k0 += 16) {
        {
            int kk = t >> 4, nl = (t & 15) * 8;
            float4 x0 = {0,0,0,0}, x1 = {0,0,0,0};
            if (k0 + kk < C) {
                const float4* s = (const float4*)(Xb + (size_t)(k0+kk)*NPTS + n0 + nl);
                x0 = s[0]; x1 = s[1];
            }
            *(float4*)&sX[kk][nl] = x0; *(float4*)&sX[kk][nl+4] = x1;
        }
#pragma unroll
        for (int i = 0; i < 8; i++) {
            int k = k0 + kb + i;
            float a = (k < C) ? Arow[k] : 0.f;
            sA2[kb + i][ar] = make_float2(a, a);
        }
        __syncthreads();
#pragma unroll
        for (int k2 = 0; k2 < 16; k2++) {
            ull a2[8], x2[4];
#pragma unroll
            for (int r = 0; r < 8; r++) a2[r] = *(const ull*)&sA2[k2][ty*8+r];
#pragma unroll
            for (int j = 0; j < 4; j++) x2[j] = *(const ull*)&sX[k2][j*32 + tx*2];
#pragma unroll
            for (int r = 0; r < 8; r++)
#pragma unroll
                for (int j = 0; j < 4; j++) fma2(acc[r][j], a2[r], x2[j]);
        }
        __syncthreads();
    }
#pragma unroll
    for (int r = 0; r < 8; r++) {
        float* dst = Out + (size_t)b*obs + (size_t)(r0 + ty*8 + r)*NPTS + n0;
#pragma unroll
        for (int j = 0; j < 4; j++)
            *(float2*)&dst[j*32 + tx*2] = make_float2(lo32(acc[r][j]), hi32(acc[r][j]));
    }
}

__global__ void k_uvt(const float* __restrict__ TUV, float* __restrict__ ut, float* __restrict__ wt, int O) {
    __shared__ float tU[32][33], tV[32][33];
    int b = blockIdx.z, n0 = blockIdx.x * 32, o0 = blockIdx.y * 32;
    int tx = threadIdx.x, ty = threadIdx.y;
#pragma unroll
    for (int r = 0; r < 4; r++) {
        int ol = ty + r*8;
        size_t iu = ((size_t)(b*2*O) + o0 + ol)*NPTS + n0 + tx;
        tU[ol][tx] = TUV[iu]; tV[ol][tx] = TUV[iu + (size_t)O*NPTS];
    }
    __syncthreads();
#pragma unroll
    for (int r = 0; r < 4; r++) {
        int nl = ty + r*8;
        size_t i = ((size_t)b*NPTS + n0 + nl)*O + o0 + tx;
        float u = tU[tx][nl]; ut[i] = u; wt[i] = tV[tx][nl] - u;
    }
}

__global__ void k_gather(const float* __restrict__ ut, const float* __restrict__ wt,
                         const int* __restrict__ IDX,
                         float* __restrict__ hmax, float* __restrict__ hmin,
                         double* __restrict__ s1g, double* __restrict__ s2g, int O) {
    int b = blockIdx.y, n0 = blockIdx.x * 8, o = threadIdx.x;
    __shared__ int sI[8*KNN_K];
    for (int l = o; l < 8*KNN_K; l += blockDim.x)
        sI[l] = IDX[((size_t)b*NPTS + n0 + l/KNN_K)*KNN_K + (l%KNN_K)];
    __syncthreads();
    const float* utb = ut + (size_t)b*NPTS*O;
    double s1a = 0.0, s2a = 0.0;
    for (int nn = 0; nn < 8; nn++) {
        float mx = -INFINITY, mn = INFINITY; float s1 = 0.f, s2 = 0.f;
#pragma unroll
        for (int k = 0; k < KNN_K; k++) {
            float v = utb[(size_t)sI[nn*KNN_K+k]*O + o];
            mx = fmaxf(mx, v); mn = fminf(mn, v); s1 += v; s2 += v*v;
        }
        size_t i = ((size_t)b*NPTS + n0 + nn)*O + o;
        float w = wt[i];
        hmax[i] = mx + w; hmin[i] = mn + w;
        s1a += (double)s1 + 20.0*(double)w;
        s2a += (double)s2 + 2.0*(double)w*(double)s1 + 20.0*(double)w*(double)w;
    }
    atomicAdd(&s1g[o], s1a); atomicAdd(&s2g[o], s2a);
}

__global__ void k_statsfin(const double* __restrict__ s1, const double* __restrict__ s2,
                           const float* __restrict__ g, const float* __restrict__ bb,
                           float* __restrict__ scale, float* __restrict__ shift, double cnt, int O) {
    int o = blockIdx.x * 256 + threadIdx.x;
    if (o >= O) return;
    double mean = s1[o] / cnt;
    double var = s2[o] / cnt - mean * mean;
    float s = g[o] * (float)(1.0 / sqrt(var + 1e-5));
    scale[o] = s; shift[o] = bb[o] - (float)mean * s;
}

__global__ void k_apply(const float* __restrict__ hmax, const float* __restrict__ hmin,
                        const float* __restrict__ scale, const float* __restrict__ shift,
                        float* __restrict__ xcat,
                        __nv_bfloat16* __restrict__ cth, __nv_bfloat16* __restrict__ ctl,
                        int O, int rowOff) {
    __shared__ float tile[32][33];
    int b = blockIdx.z, n0 = blockIdx.x * 32, o0 = blockIdx.y * 32;
    int tx = threadIdx.x, ty = threadIdx.y;
#pragma unroll
    for (int r = 0; r < 4; r++) {
        int nl = ty + r*8; int o = o0 + tx;
        float s = scale[o], t0 = shift[o];
        size_t i = ((size_t)b*NPTS + n0 + nl)*O + o;
        float hv = (s >= 0.f) ? hmax[i] : hmin[i];
        float y = s*hv + t0; y = (y >= 0.f) ? y : 0.2f*y;
        tile[nl][tx] = y;
        size_t ct = ((size_t)b*NPTS + n0 + nl)*512 + rowOff + o;
        __nv_bfloat16 hi = __float2bfloat16(y);
        cth[ct] = hi; ctl[ct] = __float2bfloat16(y - __bfloat162float(hi));
    }
    __syncthreads();
#pragma unroll
    for (int r = 0; r < 4; r++) {
        int ol = ty + r*8;
        xcat[(size_t)b*512*NPTS + (size_t)(rowOff + o0 + ol)*NPTS + n0 + tx] = tile[tx][ol];
    }
}

__global__ void k_fstats(const float* __restrict__ pf, double* __restrict__ s1o, double* __restrict__ s2o) {
    int o = blockIdx.x, t = threadIdx.x;
    double s1 = 0.0, s2 = 0.0;
    for (int l = t; l < BATCH*NPTS; l += 256) {
        int b = l >> 11, n = l & 2047;
        float v = pf[((size_t)b*1024 + o)*NPTS + n];
        s1 += (double)v; s2 += (double)v*(double)v;
    }
    __shared__ double r1[256], r2[256];
    r1[t] = s1; r2[t] = s2; __syncthreads();
    for (int off = 128; off; off >>= 1) {
        if (t < off) { r1[t] += r1[t+off]; r2[t] += r2[t+off]; }
        __syncthreads();
    }
    if (t == 0) { s1o[o] = r1[0]; s2o[o] = r2[0]; }
}

__global__ void k_out(const float* __restrict__ pf, const float* __restrict__ scale,
                      const float* __restrict__ shift, float* __restrict__ out) {
    int o = blockIdx.x, b = blockIdx.y, t = threadIdx.x;
    float s = scale[o], t0 = shift[o];
    const float* base = pf + ((size_t)b*1024 + o)*NPTS;
    { float v = base[t]; float y = s*v + t0; y = (y >= 0.f) ? y : 0.2f*y;
      out[(size_t)b*131072 + o*128 + t] = y; }
    int w = t >> 5, lane = t & 31;
#pragma unroll
    for (int i = 0; i < 4; i++) {
        int nb = w*4 + i;
        float mx = -INFINITY;
#pragma unroll
        for (int j = 0; j < 4; j++) {
            float v = base[nb*128 + lane + 32*j];
            float y = s*v + t0; y = (y >= 0.f) ? y : 0.2f*y;
            mx = fmaxf(mx, y);
        }
#pragma unroll
        for (int off = 16; off; off >>= 1) mx = fmaxf(mx, __shfl_xor_sync(0xffffffffu, mx, off));
        if (lane == 0) {
            size_t gb = 524288 + (size_t)b*32768;
            out[gb + (size_t)o*16 + nb] = mx;
            out[gb + (size_t)(o+1024)*16 + nb] = mx;
        }
    }
}

extern "C" void kernel_launch(void* const* d_in, const int* in_sizes, int n_in,
                              void* d_out, int out_size) {
    const float* x  = (const float*)d_in[0];
    const float* W[5]; for (int i = 0; i < 5; i++) W[i] = (const float*)d_in[1+i];
    const float* G[5]; const float* Bs[5];
    for (int i = 0; i < 5; i++) { G[i] = (const float*)d_in[6+2*i]; Bs[i] = (const float*)d_in[7+2*i]; }
    float* out = (float*)d_out;

    float *pD, *pXX, *pTUV, *pUT, *pWT, *pHX, *pHN, *pCAT, *pPF, *pSC, *pSH;
    double *pS1, *pS2;
    int* pIDX;
    __nv_bfloat16 *pW5h, *pW5l, *pCth, *pCtl;
    cudaGetSymbolAddress((void**)&pD, g_d);     cudaGetSymbolAddress((void**)&pXX, g_xx);
    cudaGetSymbolAddress((void**)&pTUV, g_tuv);
    cudaGetSymbolAddress((void**)&pUT, g_ut);   cudaGetSymbolAddress((void**)&pWT, g_wt);
    cudaGetSymbolAddress((void**)&pHX, g_hmax); cudaGetSymbolAddress((void**)&pHN, g_hmin);
    cudaGetSymbolAddress((void**)&pCAT, g_cat); cudaGetSymbolAddress((void**)&pPF, g_pf);
    cudaGetSymbolAddress((void**)&pS1, g_s1);   cudaGetSymbolAddress((void**)&pS2, g_s2);
    cudaGetSymbolAddress((void**)&pSC, g_scale); cudaGetSymbolAddress((void**)&pSH, g_shift);
    cudaGetSymbolAddress((void**)&pIDX, g_idx);
    cudaGetSymbolAddress((void**)&pW5h, g_w5h); cudaGetSymbolAddress((void**)&pW5l, g_w5l);
    cudaGetSymbolAddress((void**)&pCth, g_cth); cudaGetSymbolAddress((void**)&pCtl, g_ctl);

    k_w5cvt<<<2048, 256>>>(W[4], pW5h, pW5l, 1024*512);

    struct Layer { const float* X; size_t xbs; int C; int O; const float* Wm; int rowOff; };
    Layer L[4] = {
        { x,                        (size_t)3*NPTS,   3,   64,  W[0], 0   },
        { pCAT,                     (size_t)512*NPTS, 64,  64,  W[1], 64  },
        { pCAT + (size_t)64*NPTS,   (size_t)512*NPTS, 64,  128, W[2], 128 },
        { pCAT + (size_t)128*NPTS,  (size_t)512*NPTS, 128, 256, W[3], 256 },
    };

    for (int li = 0; li < 4; li++) {
        const Layer& l = L[li];
        k_xx<<<32, 256>>>(l.X, l.xbs, l.C, pXX, pS1, pS2);
        k_dist2<<<dim3(136, BATCH), 256>>>(l.X, l.xbs, pXX, pD, l.C);
        k_topk<<<dim3(NPTS, BATCH), 256>>>(pD, pIDX);
        size_t obs = (size_t)(2*l.O) * NPTS;
        k_gemmp<<<dim3(16, (2*l.O)/128, BATCH), 256>>>(l.Wm, 2*l.C, l.O, l.C,
                                                       l.X, l.xbs, pTUV, obs, l.C);
        k_uvt<<<dim3(64, l.O/32, BATCH), dim3(32, 8)>>>(pTUV, pUT, pWT, l.O);
        k_gather<<<dim3(256, BATCH), l.O>>>(pUT, pWT, pIDX, pHX, pHN, pS1, pS2, l.O);
        k_statsfin<<<(l.O + 255)/256, 256>>>(pS1, pS2, G[li], Bs[li], pSC, pSH,
                                             (double)BATCH*NPTS*KNN_K, l.O);
        k_apply<<<dim3(64, l.O/32, BATCH), dim3(32, 8)>>>(pHX, pHN, pSC, pSH, pCAT,
                                                          pCth, pCtl, l.O, l.rowOff);
    }

    k_mma_final<<<dim3(16, 8, BATCH), 256>>>(pW5h, pW5l, pCth, pCtl, pPF);
    k_fstats<<<1024, 256>>>(pPF, pS1, pS2);
    k_statsfin<<<4, 256>>>(pS1, pS2, G[4], Bs[4], pSC, pSH, (double)BATCH*NPTS, 1024);
    k_out<<<dim3(1024, BATCH), 128>>>(pPF, pSC, pSH, out);
}